// round 2
// baseline (speedup 1.0000x reference)
#include <cuda_runtime.h>
#include <math.h>

// Problem constants
#define HID 2048
#define INTER 1024
#define NEXP 8
#define NTOK 2048
#define TOPK 2
#define NPAIR (NTOK * TOPK)   // 4096

// ---------------- device scratch (no allocations allowed) ----------------
__device__ int   g_cnt[NEXP];
__device__ int   g_tok[NEXP * NPAIR];     // token id per bucket slot
__device__ float g_wt[NEXP * NPAIR];      // routing weight per bucket slot
__device__ int4  g_desc[96];              // tile: {expert, row_start, count, inter_base}
__device__ int   g_ntiles;
__device__ float g_inter[NPAIR * INTER];  // 16 MB scratch: silu(g)*u*w per pair

// ---------------- kernel 0: zero output + counters ----------------
__global__ void k_zero(float* out) {
    int i = blockIdx.x * blockDim.x + threadIdx.x;
    int total = NTOK * HID;
    for (; i < total; i += gridDim.x * blockDim.x) out[i] = 0.0f;
    if (blockIdx.x == 0 && threadIdx.x < NEXP) g_cnt[threadIdx.x] = 0;
}

// ---------------- kernel 1: route pairs into expert buckets ----------------
// NOTE: expert_indices is int32 on disk (JAX x64 disabled -> jnp.int64 request
// silently yields int32). Reading as int64 trapped with err 717 last round.
__global__ void k_route(const int* __restrict__ idx,
                        const float* __restrict__ wts) {
    int p = blockIdx.x * blockDim.x + threadIdx.x;
    if (p >= NPAIR) return;
    int e = idx[p] & 7;   // mask defensively: valid range is [0,8)
    float w = wts[p];
    int pos = atomicAdd(&g_cnt[e], 1);
    g_tok[e * NPAIR + pos] = p >> 1;   // token id
    g_wt[e * NPAIR + pos] = w;
}

// ---------------- kernel 2: build 64-row tile descriptors ----------------
__global__ void k_desc() {
    if (threadIdx.x != 0 || blockIdx.x != 0) return;
    int nt = 0, base = 0;
    for (int e = 0; e < NEXP; e++) {
        int c = g_cnt[e];
        for (int s = 0; s < c; s += 64) {
            int rows = c - s; if (rows > 64) rows = 64;
            g_desc[nt] = make_int4(e, s, rows, base + s);
            nt++;
        }
        base += c;
    }
    g_ntiles = nt;
}

// ---------------- kernel 3: fused gate+up GEMM + SwiGLU ----------------
// inter[pair, i] = silu(x·gate_e^T) * (x·up_e^T) * w     (64x64 tile, K=HID)
__global__ __launch_bounds__(256) void k_gateup(const float* __restrict__ x,
                                                const float* __restrict__ gate,
                                                const float* __restrict__ up) {
    int tile = blockIdx.y;
    if (tile >= g_ntiles) return;
    int4 d = g_desc[tile];
    int e = d.x, rs = d.y, cnt = d.z, ib = d.w;
    int ctile = blockIdx.x * 64;  // inter-column base

    __shared__ float As[16][64];
    __shared__ float Bg[16][64];
    __shared__ float Bu[16][64];
    __shared__ int   s_tok[64];
    __shared__ float s_w[64];

    int tid = threadIdx.x;
    if (tid < 64) {
        int r = tid;
        s_tok[r] = (r < cnt) ? g_tok[e * NPAIR + rs + r] : 0;
        s_w[r]   = (r < cnt) ? g_wt[e * NPAIR + rs + r] : 0.0f;
    }
    __syncthreads();

    int lr = tid >> 2;          // 0..63 row for loads
    int lc = (tid & 3) * 4;     // 0,4,8,12 col for loads
    const float* gbase = gate + (size_t)e * INTER * HID;
    const float* ubase = up   + (size_t)e * INTER * HID;

    float accg[4][4] = {}, accu[4][4] = {};
    int tr = (tid >> 4) * 4;    // output row base
    int tc = (tid & 15) * 4;    // output col base

    const float* arow = x + (size_t)s_tok[lr] * HID;
    const float* grow = gbase + (size_t)(ctile + lr) * HID;
    const float* urow = ubase + (size_t)(ctile + lr) * HID;

    for (int k0 = 0; k0 < HID; k0 += 16) {
        float4 av = *(const float4*)(arow + k0 + lc);
        float4 gv = *(const float4*)(grow + k0 + lc);
        float4 uv = *(const float4*)(urow + k0 + lc);
        As[lc + 0][lr] = av.x; As[lc + 1][lr] = av.y;
        As[lc + 2][lr] = av.z; As[lc + 3][lr] = av.w;
        Bg[lc + 0][lr] = gv.x; Bg[lc + 1][lr] = gv.y;
        Bg[lc + 2][lr] = gv.z; Bg[lc + 3][lr] = gv.w;
        Bu[lc + 0][lr] = uv.x; Bu[lc + 1][lr] = uv.y;
        Bu[lc + 2][lr] = uv.z; Bu[lc + 3][lr] = uv.w;
        __syncthreads();

        #pragma unroll
        for (int k = 0; k < 16; k++) {
            float4 a4  = *(const float4*)&As[k][tr];
            float4 bg4 = *(const float4*)&Bg[k][tc];
            float4 bu4 = *(const float4*)&Bu[k][tc];
            float a[4]  = {a4.x, a4.y, a4.z, a4.w};
            float bg[4] = {bg4.x, bg4.y, bg4.z, bg4.w};
            float bu[4] = {bu4.x, bu4.y, bu4.z, bu4.w};
            #pragma unroll
            for (int i = 0; i < 4; i++)
                #pragma unroll
                for (int j = 0; j < 4; j++) {
                    accg[i][j] = fmaf(a[i], bg[j], accg[i][j]);
                    accu[i][j] = fmaf(a[i], bu[j], accu[i][j]);
                }
        }
        __syncthreads();
    }

    // epilogue: silu(g) * u * w -> g_inter
    #pragma unroll
    for (int i = 0; i < 4; i++) {
        int r = tr + i;
        if (r < cnt) {
            float w = s_w[r];
            float o[4];
            #pragma unroll
            for (int j = 0; j < 4; j++) {
                float g = accg[i][j];
                float u = accu[i][j];
                float s = g / (1.0f + __expf(-g));
                o[j] = s * u * w;
            }
            *(float4*)&g_inter[(size_t)(ib + r) * INTER + ctile + tc] =
                make_float4(o[0], o[1], o[2], o[3]);
        }
    }
}

// ---------------- kernel 4: down GEMM + scatter-add ----------------
// out[tok, h] += inter[pair, :] · down_e[h, :]
__global__ __launch_bounds__(256) void k_down(const float* __restrict__ down,
                                              float* __restrict__ out) {
    int tile = blockIdx.y;
    if (tile >= g_ntiles) return;
    int4 d = g_desc[tile];
    int e = d.x, rs = d.y, cnt = d.z, ib = d.w;
    int ctile = blockIdx.x * 64;  // hidden-column base

    __shared__ float As[16][64];
    __shared__ float Bs[16][64];
    __shared__ int   s_tok[64];

    int tid = threadIdx.x;
    if (tid < 64) {
        int r = tid;
        s_tok[r] = (r < cnt) ? g_tok[e * NPAIR + rs + r] : 0;
    }
    __syncthreads();

    int lr = tid >> 2;
    int lc = (tid & 3) * 4;
    const float* dbase = down + (size_t)e * HID * INTER;

    int ar = (lr < cnt) ? lr : 0;  // clamp out-of-range rows (stay in bounds)
    const float* arow = g_inter + (size_t)(ib + ar) * INTER;
    const float* brow = dbase + (size_t)(ctile + lr) * INTER;

    float acc[4][4] = {};
    int tr = (tid >> 4) * 4;
    int tc = (tid & 15) * 4;

    for (int k0 = 0; k0 < INTER; k0 += 16) {
        float4 av = *(const float4*)(arow + k0 + lc);
        float4 bv = *(const float4*)(brow + k0 + lc);
        As[lc + 0][lr] = av.x; As[lc + 1][lr] = av.y;
        As[lc + 2][lr] = av.z; As[lc + 3][lr] = av.w;
        Bs[lc + 0][lr] = bv.x; Bs[lc + 1][lr] = bv.y;
        Bs[lc + 2][lr] = bv.z; Bs[lc + 3][lr] = bv.w;
        __syncthreads();

        #pragma unroll
        for (int k = 0; k < 16; k++) {
            float4 a4 = *(const float4*)&As[k][tr];
            float4 b4 = *(const float4*)&Bs[k][tc];
            float a[4] = {a4.x, a4.y, a4.z, a4.w};
            float b[4] = {b4.x, b4.y, b4.z, b4.w};
            #pragma unroll
            for (int i = 0; i < 4; i++)
                #pragma unroll
                for (int j = 0; j < 4; j++)
                    acc[i][j] = fmaf(a[i], b[j], acc[i][j]);
        }
        __syncthreads();
    }

    #pragma unroll
    for (int i = 0; i < 4; i++) {
        int r = tr + i;
        if (r < cnt) {
            float* orow = out + (size_t)s_tok[r] * HID + ctile + tc;
            #pragma unroll
            for (int j = 0; j < 4; j++)
                atomicAdd(orow + j, acc[i][j]);
        }
    }
}

// ---------------- launch ----------------
extern "C" void kernel_launch(void* const* d_in, const int* in_sizes, int n_in,
                              void* d_out, int out_size) {
    const float* x    = (const float*)d_in[0];
    const int*   eidx = (const int*)d_in[1];
    const float* ewt  = (const float*)d_in[2];
    const float* gate = (const float*)d_in[3];
    const float* up   = (const float*)d_in[4];
    const float* down = (const float*)d_in[5];
    float* out = (float*)d_out;

    k_zero<<<2048, 256>>>(out);
    k_route<<<(NPAIR + 255) / 256, 256>>>(eidx, ewt);
    k_desc<<<1, 32>>>();

    // max tiles = 4096/64 + (NEXP-1) = 71 -> use 72
    dim3 g2(INTER / 64, 72);
    k_gateup<<<g2, 256>>>(x, gate, up);

    dim3 g3(HID / 64, 72);
    k_down<<<g3, 256>>>(down, out);
}

// round 3
// speedup vs baseline: 2.6178x; 2.6178x over previous
#include <cuda_runtime.h>
#include <math.h>

// Problem constants
#define HID 2048
#define INTER 1024
#define NEXP 8
#define NTOK 2048
#define TOPK 2
#define NPAIR (NTOK * TOPK)   // 4096

// ---------------- device scratch ----------------
__device__ int   g_cnt[NEXP];
__device__ int   g_tok[NEXP * NPAIR];
__device__ float g_wt[NEXP * NPAIR];
__device__ int4  g_desc[96];              // {expert, row_start, count, inter_base}
__device__ int   g_ntiles;
__device__ float g_inter[NPAIR * INTER];  // 16 MB scratch

// ---------------- helpers ----------------
__device__ __forceinline__ unsigned f2tf32(float f) {
    unsigned r;
    asm("cvt.rna.tf32.f32 %0, %1;" : "=r"(r) : "f"(f));
    return r;
}

#define MMA_TF32(c, a0, a1, a2, a3, b0, b1)                                   \
    asm volatile(                                                             \
        "mma.sync.aligned.m16n8k8.row.col.f32.tf32.tf32.f32 "                 \
        "{%0,%1,%2,%3}, {%4,%5,%6,%7}, {%8,%9}, {%0,%1,%2,%3};"               \
        : "+f"((c)[0]), "+f"((c)[1]), "+f"((c)[2]), "+f"((c)[3])              \
        : "r"(a0), "r"(a1), "r"(a2), "r"(a3), "r"(b0), "r"(b1))

#define KC 32
#define LDK 36   // padded stride: bank = (4*row + lx) % 32 -> conflict-free frags

// ---------------- kernel 0: zero output + counters ----------------
__global__ void k_zero(float* out) {
    int i = blockIdx.x * blockDim.x + threadIdx.x;
    int total = NTOK * HID;
    for (; i < total; i += gridDim.x * blockDim.x) out[i] = 0.0f;
    if (blockIdx.x == 0 && threadIdx.x < NEXP) g_cnt[threadIdx.x] = 0;
}

// ---------------- kernel 1: route ----------------
__global__ void k_route(const int* __restrict__ idx,
                        const float* __restrict__ wts) {
    int p = blockIdx.x * blockDim.x + threadIdx.x;
    if (p >= NPAIR) return;
    int e = idx[p] & 7;
    float w = wts[p];
    int pos = atomicAdd(&g_cnt[e], 1);
    g_tok[e * NPAIR + pos] = p >> 1;
    g_wt[e * NPAIR + pos] = w;
}

// ---------------- kernel 2: tile descriptors ----------------
__global__ void k_desc() {
    if (threadIdx.x != 0 || blockIdx.x != 0) return;
    int nt = 0, base = 0;
    for (int e = 0; e < NEXP; e++) {
        int c = g_cnt[e];
        for (int s = 0; s < c; s += 64) {
            int rows = c - s; if (rows > 64) rows = 64;
            g_desc[nt] = make_int4(e, s, rows, base + s);
            nt++;
        }
        base += c;
    }
    g_ntiles = nt;
}

// ---------------- kernel 3: gate+up tf32 MMA + SwiGLU ----------------
// 64 pairs x 64 inter cols per block; warp = 16x32 microtile of BOTH gate & up.
__global__ __launch_bounds__(256) void k_gateup(const float* __restrict__ x,
                                                const float* __restrict__ gate,
                                                const float* __restrict__ up) {
    int tile = blockIdx.y;
    if (tile >= g_ntiles) return;
    int4 d = g_desc[tile];
    int e = d.x, rs = d.y, cnt = d.z, ib = d.w;
    int ctile = blockIdx.x * 64;

    __shared__ unsigned As[64 * LDK];
    __shared__ unsigned Gs[64 * LDK];
    __shared__ unsigned Us[64 * LDK];
    __shared__ int   s_tok[64];
    __shared__ float s_w[64];

    int tid = threadIdx.x;
    if (tid < 64) {
        s_tok[tid] = (tid < cnt) ? g_tok[e * NPAIR + rs + tid] : 0;
        s_w[tid]   = (tid < cnt) ? g_wt[e * NPAIR + rs + tid] : 0.0f;
    }
    __syncthreads();

    int lrow = tid >> 2;          // 0..63
    int lcol = (tid & 3) * 8;     // 0,8,16,24

    const float* arow = x + (size_t)s_tok[lrow] * HID + lcol;
    const float* grow = gate + (size_t)e * INTER * HID + (size_t)(ctile + lrow) * HID + lcol;
    const float* urow = up   + (size_t)e * INTER * HID + (size_t)(ctile + lrow) * HID + lcol;

    int lane = tid & 31, warp = tid >> 5;
    int mg = (warp & 3) * 16;     // m base
    int nh = (warp >> 2) * 32;    // n base
    int ly = lane >> 2, lx = lane & 3;

    float accg[4][4] = {}, accu[4][4] = {};

    for (int k0 = 0; k0 < HID; k0 += KC) {
        float4 a0 = *(const float4*)(arow + k0);
        float4 a1 = *(const float4*)(arow + k0 + 4);
        float4 g0 = *(const float4*)(grow + k0);
        float4 g1 = *(const float4*)(grow + k0 + 4);
        float4 u0 = *(const float4*)(urow + k0);
        float4 u1 = *(const float4*)(urow + k0 + 4);
        unsigned* pa = &As[lrow * LDK + lcol];
        unsigned* pg = &Gs[lrow * LDK + lcol];
        unsigned* pu = &Us[lrow * LDK + lcol];
        pa[0]=f2tf32(a0.x); pa[1]=f2tf32(a0.y); pa[2]=f2tf32(a0.z); pa[3]=f2tf32(a0.w);
        pa[4]=f2tf32(a1.x); pa[5]=f2tf32(a1.y); pa[6]=f2tf32(a1.z); pa[7]=f2tf32(a1.w);
        pg[0]=f2tf32(g0.x); pg[1]=f2tf32(g0.y); pg[2]=f2tf32(g0.z); pg[3]=f2tf32(g0.w);
        pg[4]=f2tf32(g1.x); pg[5]=f2tf32(g1.y); pg[6]=f2tf32(g1.z); pg[7]=f2tf32(g1.w);
        pu[0]=f2tf32(u0.x); pu[1]=f2tf32(u0.y); pu[2]=f2tf32(u0.z); pu[3]=f2tf32(u0.w);
        pu[4]=f2tf32(u1.x); pu[5]=f2tf32(u1.y); pu[6]=f2tf32(u1.z); pu[7]=f2tf32(u1.w);
        __syncthreads();

        #pragma unroll
        for (int kk = 0; kk < KC; kk += 8) {
            unsigned fa0 = As[(mg + ly) * LDK + kk + lx];
            unsigned fa1 = As[(mg + ly + 8) * LDK + kk + lx];
            unsigned fa2 = As[(mg + ly) * LDK + kk + lx + 4];
            unsigned fa3 = As[(mg + ly + 8) * LDK + kk + lx + 4];
            #pragma unroll
            for (int j = 0; j < 4; j++) {
                int n = (nh + j * 8 + ly) * LDK + kk;
                unsigned bg0 = Gs[n + lx], bg1 = Gs[n + lx + 4];
                MMA_TF32(accg[j], fa0, fa1, fa2, fa3, bg0, bg1);
                unsigned bu0 = Us[n + lx], bu1 = Us[n + lx + 4];
                MMA_TF32(accu[j], fa0, fa1, fa2, fa3, bu0, bu1);
            }
        }
        __syncthreads();
    }

    // epilogue: silu(g)*u*w -> g_inter
    int r0 = mg + ly, r1 = mg + ly + 8;
    #pragma unroll
    for (int j = 0; j < 4; j++) {
        int c = ctile + nh + j * 8 + 2 * lx;
        if (r0 < cnt) {
            float w = s_w[r0];
            float ga = accg[j][0], ua = accu[j][0];
            float gb = accg[j][1], ub = accu[j][1];
            float o0 = ga / (1.0f + __expf(-ga)) * ua * w;
            float o1 = gb / (1.0f + __expf(-gb)) * ub * w;
            *(float2*)&g_inter[(size_t)(ib + r0) * INTER + c] = make_float2(o0, o1);
        }
        if (r1 < cnt) {
            float w = s_w[r1];
            float ga = accg[j][2], ua = accu[j][2];
            float gb = accg[j][3], ub = accu[j][3];
            float o0 = ga / (1.0f + __expf(-ga)) * ua * w;
            float o1 = gb / (1.0f + __expf(-gb)) * ub * w;
            *(float2*)&g_inter[(size_t)(ib + r1) * INTER + c] = make_float2(o0, o1);
        }
    }
}

// ---------------- kernel 4: down tf32 MMA + scatter-add ----------------
__global__ __launch_bounds__(256) void k_down(const float* __restrict__ down,
                                              float* __restrict__ out) {
    int tile = blockIdx.y;
    if (tile >= g_ntiles) return;
    int4 d = g_desc[tile];
    int e = d.x, rs = d.y, cnt = d.z, ib = d.w;
    int ctile = blockIdx.x * 64;   // hidden-column base

    __shared__ unsigned As[64 * LDK];
    __shared__ unsigned Bs[64 * LDK];
    __shared__ int s_tok[64];

    int tid = threadIdx.x;
    if (tid < 64)
        s_tok[tid] = (tid < cnt) ? g_tok[e * NPAIR + rs + tid] : 0;
    __syncthreads();

    int lrow = tid >> 2;
    int lcol = (tid & 3) * 8;

    int arIdx = ib + ((lrow < cnt) ? lrow : (cnt - 1));   // clamp: stay in g_inter
    const float* arow = g_inter + (size_t)arIdx * INTER + lcol;
    const float* brow = down + (size_t)e * HID * INTER + (size_t)(ctile + lrow) * INTER + lcol;

    int lane = tid & 31, warp = tid >> 5;
    int mg = (warp & 3) * 16;
    int nh = (warp >> 2) * 32;
    int ly = lane >> 2, lx = lane & 3;

    float acc[4][4] = {};

    for (int k0 = 0; k0 < INTER; k0 += KC) {
        float4 a0 = *(const float4*)(arow + k0);
        float4 a1 = *(const float4*)(arow + k0 + 4);
        float4 b0 = *(const float4*)(brow + k0);
        float4 b1 = *(const float4*)(brow + k0 + 4);
        unsigned* pa = &As[lrow * LDK + lcol];
        unsigned* pb = &Bs[lrow * LDK + lcol];
        pa[0]=f2tf32(a0.x); pa[1]=f2tf32(a0.y); pa[2]=f2tf32(a0.z); pa[3]=f2tf32(a0.w);
        pa[4]=f2tf32(a1.x); pa[5]=f2tf32(a1.y); pa[6]=f2tf32(a1.z); pa[7]=f2tf32(a1.w);
        pb[0]=f2tf32(b0.x); pb[1]=f2tf32(b0.y); pb[2]=f2tf32(b0.z); pb[3]=f2tf32(b0.w);
        pb[4]=f2tf32(b1.x); pb[5]=f2tf32(b1.y); pb[6]=f2tf32(b1.z); pb[7]=f2tf32(b1.w);
        __syncthreads();

        #pragma unroll
        for (int kk = 0; kk < KC; kk += 8) {
            unsigned fa0 = As[(mg + ly) * LDK + kk + lx];
            unsigned fa1 = As[(mg + ly + 8) * LDK + kk + lx];
            unsigned fa2 = As[(mg + ly) * LDK + kk + lx + 4];
            unsigned fa3 = As[(mg + ly + 8) * LDK + kk + lx + 4];
            #pragma unroll
            for (int j = 0; j < 4; j++) {
                int n = (nh + j * 8 + ly) * LDK + kk;
                unsigned fb0 = Bs[n + lx], fb1 = Bs[n + lx + 4];
                MMA_TF32(acc[j], fa0, fa1, fa2, fa3, fb0, fb1);
            }
        }
        __syncthreads();
    }

    int r0 = mg + ly, r1 = mg + ly + 8;
    #pragma unroll
    for (int j = 0; j < 4; j++) {
        int c = ctile + nh + j * 8 + 2 * lx;
        if (r0 < cnt) {
            float* o = out + (size_t)s_tok[r0] * HID + c;
            atomicAdd(o, acc[j][0]);
            atomicAdd(o + 1, acc[j][1]);
        }
        if (r1 < cnt) {
            float* o = out + (size_t)s_tok[r1] * HID + c;
            atomicAdd(o, acc[j][2]);
            atomicAdd(o + 1, acc[j][3]);
        }
    }
}

// ---------------- launch ----------------
extern "C" void kernel_launch(void* const* d_in, const int* in_sizes, int n_in,
                              void* d_out, int out_size) {
    const float* x    = (const float*)d_in[0];
    const int*   eidx = (const int*)d_in[1];
    const float* ewt  = (const float*)d_in[2];
    const float* gate = (const float*)d_in[3];
    const float* up   = (const float*)d_in[4];
    const float* down = (const float*)d_in[5];
    float* out = (float*)d_out;

    k_zero<<<2048, 256>>>(out);
    k_route<<<(NPAIR + 255) / 256, 256>>>(eidx, ewt);
    k_desc<<<1, 32>>>();

    dim3 g2(INTER / 64, 72);
    k_gateup<<<g2, 256>>>(x, gate, up);

    dim3 g3(HID / 64, 72);
    k_down<<<g3, 256>>>(down, out);
}

// round 4
// speedup vs baseline: 2.8605x; 1.0927x over previous
#include <cuda_runtime.h>
#include <math.h>

// Problem constants
#define HID 2048
#define INTER 1024
#define NEXP 8
#define NTOK 2048
#define TOPK 2
#define NPAIR (NTOK * TOPK)   // 4096

#define KC 32
#define LDK 36   // padded word stride -> conflict-free ldmatrix/STS phases

// ---------------- device scratch ----------------
__device__ int   g_cnt[NEXP];
__device__ int   g_tok[NEXP * NPAIR];
__device__ float g_wt[NEXP * NPAIR];
__device__ int4  g_desc[96];              // {expert, row_start, count, inter_base}
__device__ int   g_ntiles;
__device__ float g_inter[NPAIR * INTER];  // 16 MB scratch

// ---------------- helpers ----------------
__device__ __forceinline__ unsigned f2tf32(float f) {
    unsigned r;
    asm("cvt.rna.tf32.f32 %0, %1;" : "=r"(r) : "f"(f));
    return r;
}

__device__ __forceinline__ void st_tf32x4(unsigned* p, float4 v) {
    uint4 o;
    o.x = f2tf32(v.x); o.y = f2tf32(v.y); o.z = f2tf32(v.z); o.w = f2tf32(v.w);
    *(uint4*)p = o;
}

// ldmatrix x4 (b16 form): 4 tiles of 8 rows x 16B
__device__ __forceinline__ void ldm4(unsigned& r0, unsigned& r1, unsigned& r2,
                                     unsigned& r3, const unsigned* ptr) {
    unsigned addr = (unsigned)__cvta_generic_to_shared(ptr);
    asm volatile("ldmatrix.sync.aligned.m8n8.x4.shared.b16 {%0,%1,%2,%3}, [%4];"
                 : "=r"(r0), "=r"(r1), "=r"(r2), "=r"(r3) : "r"(addr));
}

#define MMA_TF32(c, a0, a1, a2, a3, b0, b1)                                   \
    asm volatile(                                                             \
        "mma.sync.aligned.m16n8k8.row.col.f32.tf32.tf32.f32 "                 \
        "{%0,%1,%2,%3}, {%4,%5,%6,%7}, {%8,%9}, {%0,%1,%2,%3};"               \
        : "+f"((c)[0]), "+f"((c)[1]), "+f"((c)[2]), "+f"((c)[3])              \
        : "r"(a0), "r"(a1), "r"(a2), "r"(a3), "r"(b0), "r"(b1))

// ---------------- kernel 0: zero output + counters ----------------
__global__ void k_zero(float* out) {
    int i = blockIdx.x * blockDim.x + threadIdx.x;
    int total = NTOK * HID;
    for (; i < total; i += gridDim.x * blockDim.x) out[i] = 0.0f;
    if (blockIdx.x == 0 && threadIdx.x < NEXP) g_cnt[threadIdx.x] = 0;
}

// ---------------- kernel 1: route ----------------
__global__ void k_route(const int* __restrict__ idx,
                        const float* __restrict__ wts) {
    int p = blockIdx.x * blockDim.x + threadIdx.x;
    if (p >= NPAIR) return;
    int e = idx[p] & 7;
    float w = wts[p];
    int pos = atomicAdd(&g_cnt[e], 1);
    g_tok[e * NPAIR + pos] = p >> 1;
    g_wt[e * NPAIR + pos] = w;
}

// ---------------- kernel 2: tile descriptors ----------------
__global__ void k_desc() {
    if (threadIdx.x != 0 || blockIdx.x != 0) return;
    int nt = 0, base = 0;
    for (int e = 0; e < NEXP; e++) {
        int c = g_cnt[e];
        for (int s = 0; s < c; s += 64) {
            int rows = c - s; if (rows > 64) rows = 64;
            g_desc[nt] = make_int4(e, s, rows, base + s);
            nt++;
        }
        base += c;
    }
    g_ntiles = nt;
}

// ---------------- kernel 3: gate+up tf32 MMA + SwiGLU ----------------
// Block tile: 64 pairs x 128 inter cols. Warps 2(m) x 4(n); warp tile 32x32
// of BOTH gate and up. ldmatrix.x4 fragment loads.
__global__ __launch_bounds__(256) void k_gateup(const float* __restrict__ x,
                                                const float* __restrict__ gate,
                                                const float* __restrict__ up) {
    int tile = blockIdx.y;
    if (tile >= g_ntiles) return;
    int4 d = g_desc[tile];
    int e = d.x, rs = d.y, cnt = d.z, ib = d.w;
    int ctile = blockIdx.x * 128;

    __shared__ unsigned As[64 * LDK];
    __shared__ unsigned Gs[128 * LDK];
    __shared__ unsigned Us[128 * LDK];
    __shared__ int   s_tok[64];
    __shared__ float s_w[64];

    int tid = threadIdx.x;
    if (tid < 64) {
        s_tok[tid] = (tid < cnt) ? g_tok[e * NPAIR + rs + tid] : 0;
        s_w[tid]   = (tid < cnt) ? g_wt[e * NPAIR + rs + tid] : 0.0f;
    }
    __syncthreads();

    // global load mapping
    int aRow = tid >> 2, aCg = (tid & 3) * 8;         // A: 64 rows, 8 floats/thread
    int bRow = tid >> 1, bCg = (tid & 1) * 16;        // G/U: 128 rows, 16 floats/thread
    const float* arow = x + (size_t)s_tok[aRow] * HID + aCg;
    const float* grow = gate + (size_t)e * INTER * HID + (size_t)(ctile + bRow) * HID + bCg;
    const float* urow = up   + (size_t)e * INTER * HID + (size_t)(ctile + bRow) * HID + bCg;

    int lane = tid & 31, warp = tid >> 5;
    int mg = (warp & 1) * 32;       // warp m base (0/32)
    int nh = (warp >> 1) * 32;      // warp n base (0..96)
    int ly = lane >> 2, lx = lane & 3;

    // ldmatrix lane addressing
    int aR = (lane & 15), aC = (lane >> 4) << 2;               // A frag tiles
    int bR = (lane & 7) + ((lane & 16) ? 8 : 0);               // B frag tiles
    int bC = (lane & 8) ? 4 : 0;

    float accg[2][4][4] = {}, accu[2][4][4] = {};

    for (int k0 = 0; k0 < HID; k0 += KC) {
        st_tf32x4(&As[aRow * LDK + aCg],     *(const float4*)(arow + k0));
        st_tf32x4(&As[aRow * LDK + aCg + 4], *(const float4*)(arow + k0 + 4));
        #pragma unroll
        for (int q = 0; q < 4; q++) {
            st_tf32x4(&Gs[bRow * LDK + bCg + 4 * q], *(const float4*)(grow + k0 + 4 * q));
            st_tf32x4(&Us[bRow * LDK + bCg + 4 * q], *(const float4*)(urow + k0 + 4 * q));
        }
        __syncthreads();

        #pragma unroll
        for (int kk = 0; kk < KC; kk += 8) {
            unsigned a[2][4];
            ldm4(a[0][0], a[0][1], a[0][2], a[0][3], &As[(mg + aR) * LDK + kk + aC]);
            ldm4(a[1][0], a[1][1], a[1][2], a[1][3], &As[(mg + 16 + aR) * LDK + kk + aC]);

            unsigned g0, g1, g2, g3, g4, g5, g6, g7;
            ldm4(g0, g1, g2, g3, &Gs[(nh + bR) * LDK + kk + bC]);
            ldm4(g4, g5, g6, g7, &Gs[(nh + 16 + bR) * LDK + kk + bC]);
            unsigned u0, u1, u2, u3, u4, u5, u6, u7;
            ldm4(u0, u1, u2, u3, &Us[(nh + bR) * LDK + kk + bC]);
            ldm4(u4, u5, u6, u7, &Us[(nh + 16 + bR) * LDK + kk + bC]);

            #pragma unroll
            for (int mi = 0; mi < 2; mi++) {
                MMA_TF32(accg[mi][0], a[mi][0], a[mi][1], a[mi][2], a[mi][3], g0, g1);
                MMA_TF32(accg[mi][1], a[mi][0], a[mi][1], a[mi][2], a[mi][3], g2, g3);
                MMA_TF32(accg[mi][2], a[mi][0], a[mi][1], a[mi][2], a[mi][3], g4, g5);
                MMA_TF32(accg[mi][3], a[mi][0], a[mi][1], a[mi][2], a[mi][3], g6, g7);
                MMA_TF32(accu[mi][0], a[mi][0], a[mi][1], a[mi][2], a[mi][3], u0, u1);
                MMA_TF32(accu[mi][1], a[mi][0], a[mi][1], a[mi][2], a[mi][3], u2, u3);
                MMA_TF32(accu[mi][2], a[mi][0], a[mi][1], a[mi][2], a[mi][3], u4, u5);
                MMA_TF32(accu[mi][3], a[mi][0], a[mi][1], a[mi][2], a[mi][3], u6, u7);
            }
        }
        __syncthreads();
    }

    // epilogue: silu(g)*u*w -> g_inter
    #pragma unroll
    for (int mi = 0; mi < 2; mi++) {
        int r0 = mg + mi * 16 + ly, r1 = r0 + 8;
        #pragma unroll
        for (int j = 0; j < 4; j++) {
            int c = ctile + nh + j * 8 + 2 * lx;
            if (r0 < cnt) {
                float w = s_w[r0];
                float ga = accg[mi][j][0], ua = accu[mi][j][0];
                float gb = accg[mi][j][1], ub = accu[mi][j][1];
                float o0 = ga / (1.0f + __expf(-ga)) * ua * w;
                float o1 = gb / (1.0f + __expf(-gb)) * ub * w;
                *(float2*)&g_inter[(size_t)(ib + r0) * INTER + c] = make_float2(o0, o1);
            }
            if (r1 < cnt) {
                float w = s_w[r1];
                float ga = accg[mi][j][2], ua = accu[mi][j][2];
                float gb = accg[mi][j][3], ub = accu[mi][j][3];
                float o0 = ga / (1.0f + __expf(-ga)) * ua * w;
                float o1 = gb / (1.0f + __expf(-gb)) * ub * w;
                *(float2*)&g_inter[(size_t)(ib + r1) * INTER + c] = make_float2(o0, o1);
            }
        }
    }
}

// ---------------- kernel 4: down tf32 MMA + scatter-add ----------------
// Block tile: 64 pairs x 128 hid cols. Warps 2(m) x 4(n); warp tile 32x32.
__global__ __launch_bounds__(256) void k_down(const float* __restrict__ down,
                                              float* __restrict__ out) {
    int tile = blockIdx.y;
    if (tile >= g_ntiles) return;
    int4 d = g_desc[tile];
    int e = d.x, rs = d.y, cnt = d.z, ib = d.w;
    int ctile = blockIdx.x * 128;

    __shared__ unsigned As[64 * LDK];
    __shared__ unsigned Bs[128 * LDK];
    __shared__ int s_tok[64];

    int tid = threadIdx.x;
    if (tid < 64)
        s_tok[tid] = (tid < cnt) ? g_tok[e * NPAIR + rs + tid] : 0;
    __syncthreads();

    int aRow = tid >> 2, aCg = (tid & 3) * 8;
    int bRow = tid >> 1, bCg = (tid & 1) * 16;
    int arIdx = ib + ((aRow < cnt) ? aRow : (cnt - 1));
    const float* arow = g_inter + (size_t)arIdx * INTER + aCg;
    const float* brow = down + (size_t)e * HID * INTER + (size_t)(ctile + bRow) * INTER + bCg;

    int lane = tid & 31, warp = tid >> 5;
    int mg = (warp & 1) * 32;
    int nh = (warp >> 1) * 32;
    int ly = lane >> 2, lx = lane & 3;

    int aR = (lane & 15), aC = (lane >> 4) << 2;
    int bR = (lane & 7) + ((lane & 16) ? 8 : 0);
    int bC = (lane & 8) ? 4 : 0;

    float acc[2][4][4] = {};

    for (int k0 = 0; k0 < INTER; k0 += KC) {
        st_tf32x4(&As[aRow * LDK + aCg],     *(const float4*)(arow + k0));
        st_tf32x4(&As[aRow * LDK + aCg + 4], *(const float4*)(arow + k0 + 4));
        #pragma unroll
        for (int q = 0; q < 4; q++)
            st_tf32x4(&Bs[bRow * LDK + bCg + 4 * q], *(const float4*)(brow + k0 + 4 * q));
        __syncthreads();

        #pragma unroll
        for (int kk = 0; kk < KC; kk += 8) {
            unsigned a[2][4];
            ldm4(a[0][0], a[0][1], a[0][2], a[0][3], &As[(mg + aR) * LDK + kk + aC]);
            ldm4(a[1][0], a[1][1], a[1][2], a[1][3], &As[(mg + 16 + aR) * LDK + kk + aC]);

            unsigned b0, b1, b2, b3, b4, b5, b6, b7;
            ldm4(b0, b1, b2, b3, &Bs[(nh + bR) * LDK + kk + bC]);
            ldm4(b4, b5, b6, b7, &Bs[(nh + 16 + bR) * LDK + kk + bC]);

            #pragma unroll
            for (int mi = 0; mi < 2; mi++) {
                MMA_TF32(acc[mi][0], a[mi][0], a[mi][1], a[mi][2], a[mi][3], b0, b1);
                MMA_TF32(acc[mi][1], a[mi][0], a[mi][1], a[mi][2], a[mi][3], b2, b3);
                MMA_TF32(acc[mi][2], a[mi][0], a[mi][1], a[mi][2], a[mi][3], b4, b5);
                MMA_TF32(acc[mi][3], a[mi][0], a[mi][1], a[mi][2], a[mi][3], b6, b7);
            }
        }
        __syncthreads();
    }

    #pragma unroll
    for (int mi = 0; mi < 2; mi++) {
        int r0 = mg + mi * 16 + ly, r1 = r0 + 8;
        #pragma unroll
        for (int j = 0; j < 4; j++) {
            int c = ctile + nh + j * 8 + 2 * lx;
            if (r0 < cnt) {
                float* o = out + (size_t)s_tok[r0] * HID + c;
                atomicAdd(o,     acc[mi][j][0]);
                atomicAdd(o + 1, acc[mi][j][1]);
            }
            if (r1 < cnt) {
                float* o = out + (size_t)s_tok[r1] * HID + c;
                atomicAdd(o,     acc[mi][j][2]);
                atomicAdd(o + 1, acc[mi][j][3]);
            }
        }
    }
}

// ---------------- launch ----------------
extern "C" void kernel_launch(void* const* d_in, const int* in_sizes, int n_in,
                              void* d_out, int out_size) {
    const float* x    = (const float*)d_in[0];
    const int*   eidx = (const int*)d_in[1];
    const float* ewt  = (const float*)d_in[2];
    const float* gate = (const float*)d_in[3];
    const float* up   = (const float*)d_in[4];
    const float* down = (const float*)d_in[5];
    float* out = (float*)d_out;

    k_zero<<<2048, 256>>>(out);
    k_route<<<(NPAIR + 255) / 256, 256>>>(eidx, ewt);
    k_desc<<<1, 32>>>();

    dim3 g2(INTER / 128, 72);
    k_gateup<<<g2, 256>>>(x, gate, up);

    dim3 g3(HID / 128, 72);
    k_down<<<g3, 256>>>(down, out);
}

// round 6
// speedup vs baseline: 5.3615x; 1.8743x over previous
#include <cuda_runtime.h>
#include <cuda_fp16.h>
#include <math.h>
#include <cstdint>

// Problem constants
#define HID 2048
#define INTER 1024
#define NEXP 8
#define NTOK 2048
#define TOPK 2
#define NPAIR (NTOK * TOPK)   // 4096

#define TM 64                 // pair-rows per tile
#define KC 32                 // K halves per chunk (64B per logical row)

// ---------------- device scratch ----------------
__device__ int    g_cnt[NEXP];
__device__ int    g_tok[NEXP * NPAIR];
__device__ float  g_wt[NEXP * NPAIR];
__device__ int4   g_desc[96];             // {expert, row_start, count, inter_base}
__device__ int    g_ntiles;
__device__ __half gh_x[NTOK * HID];                 // 8.4 MB
__device__ __half gh_gate[NEXP * INTER * HID];      // 33.5 MB
__device__ __half gh_up[NEXP * INTER * HID];        // 33.5 MB
__device__ __half gh_down[NEXP * HID * INTER];      // 33.5 MB
__device__ __half g_inter[(NPAIR + TM) * INTER];    // 8.4 MB

// ---------------- helpers ----------------
// ldmatrix x4 (b16): 4 tiles of 8 rows x 16B; one row-address per lane.
__device__ __forceinline__ void ldm4(unsigned& r0, unsigned& r1, unsigned& r2,
                                     unsigned& r3, const void* ptr) {
    unsigned addr = (unsigned)__cvta_generic_to_shared(ptr);
    asm volatile("ldmatrix.sync.aligned.m8n8.x4.shared.b16 {%0,%1,%2,%3}, [%4];"
                 : "=r"(r0), "=r"(r1), "=r"(r2), "=r"(r3) : "r"(addr));
}

#define MMA_F16(c, a, b0, b1)                                                 \
    asm volatile(                                                             \
        "mma.sync.aligned.m16n8k16.row.col.f32.f16.f16.f32 "                  \
        "{%0,%1,%2,%3}, {%4,%5,%6,%7}, {%8,%9}, {%0,%1,%2,%3};"               \
        : "+f"((c)[0]), "+f"((c)[1]), "+f"((c)[2]), "+f"((c)[3])              \
        : "r"((a)[0]), "r"((a)[1]), "r"((a)[2]), "r"((a)[3]), "r"(b0), "r"(b1))

// Paired-row XOR swizzle: logical (row, 16B-group g in 0..3) -> uint4 index.
// Two 64B logical rows share one 128B smem row; group XOR'd by (srow&7).
// Conflict-free for STS (lanes = 2 rows x 4 groups) and all ldmatrix phases
// (8 consecutive rows, fixed g).
__device__ __forceinline__ int swzi(int row, int g) {
    int srow = row >> 1;
    return srow * 8 + ((((row & 1) << 2) | g) ^ (srow & 7));
}

// ---------------- kernel 0: zero output + counters ----------------
__global__ void k_zero(float* out) {
    int i = blockIdx.x * blockDim.x + threadIdx.x;
    int total = NTOK * HID;
    for (; i < total; i += gridDim.x * blockDim.x) out[i] = 0.0f;
    if (blockIdx.x == 0 && threadIdx.x < NEXP) g_cnt[threadIdx.x] = 0;
}

// ---------------- kernel 1: route ----------------
__global__ void k_route(const int* __restrict__ idx,
                        const float* __restrict__ wts) {
    int p = blockIdx.x * blockDim.x + threadIdx.x;
    if (p >= NPAIR) return;
    int e = idx[p] & 7;
    float w = wts[p];
    int pos = atomicAdd(&g_cnt[e], 1);
    g_tok[e * NPAIR + pos] = p >> 1;
    g_wt[e * NPAIR + pos] = w;
}

// ---------------- kernel 2: tile descriptors ----------------
__global__ void k_desc() {
    if (threadIdx.x != 0 || blockIdx.x != 0) return;
    int nt = 0, base = 0;
    for (int e = 0; e < NEXP; e++) {
        int c = g_cnt[e];
        for (int s = 0; s < c; s += TM) {
            int rows = c - s; if (rows > TM) rows = TM;
            g_desc[nt] = make_int4(e, s, rows, base + s);
            nt++;
        }
        base += c;
    }
    g_ntiles = nt;
}

// ---------------- kernel: fp32 -> fp16 pre-convert (weights + x) ----------
__global__ void k_cvtall(const float4* __restrict__ gate,
                         const float4* __restrict__ up,
                         const float4* __restrict__ down,
                         const float4* __restrict__ x) {
    const int NW8 = NEXP * INTER * HID / 8;   // 2097152
    const int NX8 = NTOK * HID / 8;           // 524288
    int total = 3 * NW8 + NX8;
    for (int i = blockIdx.x * blockDim.x + threadIdx.x; i < total;
         i += gridDim.x * blockDim.x) {
        const float4* src; uint4* dst; int j;
        if (i < NW8)          { src = gate; dst = (uint4*)gh_gate; j = i; }
        else if (i < 2 * NW8) { src = up;   dst = (uint4*)gh_up;   j = i - NW8; }
        else if (i < 3 * NW8) { src = down; dst = (uint4*)gh_down; j = i - 2 * NW8; }
        else                  { src = x;    dst = (uint4*)gh_x;    j = i - 3 * NW8; }
        float4 f0 = src[2 * j], f1 = src[2 * j + 1];
        __half2 h0 = __floats2half2_rn(f0.x, f0.y);
        __half2 h1 = __floats2half2_rn(f0.z, f0.w);
        __half2 h2 = __floats2half2_rn(f1.x, f1.y);
        __half2 h3 = __floats2half2_rn(f1.z, f1.w);
        uint4 o;
        o.x = *(unsigned*)&h0; o.y = *(unsigned*)&h1;
        o.z = *(unsigned*)&h2; o.w = *(unsigned*)&h3;
        dst[j] = o;
    }
}

// ---------------- kernel 3: fp16 MMA gate+up + SwiGLU ----------------
// Block tile: 64 pairs x 128 inter cols, both matrices. Warps 2(m) x 4(n),
// warp tile 32x32 per matrix. Register-prefetched 2-stage smem pipeline.
__global__ __launch_bounds__(256, 2) void k_gateup() {
    int tile = blockIdx.y;
    if (tile >= g_ntiles) return;
    int4 d = g_desc[tile];
    int e = d.x, rs = d.y, cnt = d.z, ib = d.w;
    int ctile = blockIdx.x * 128;

    __shared__ uint4 sA[2][256];   // 64 rows x 32 halves, swizzled
    __shared__ uint4 sG[2][512];   // 128 rows x 32 halves
    __shared__ uint4 sU[2][512];
    __shared__ int   s_tok[TM];
    __shared__ float s_w[TM];

    int tid = threadIdx.x, lane = tid & 31, warp = tid >> 5;
    if (tid < TM) {
        s_tok[tid] = (tid < cnt) ? g_tok[e * NPAIR + rs + tid] : g_tok[e * NPAIR + rs];
        s_w[tid]   = (tid < cnt) ? g_wt[e * NPAIR + rs + tid] : 0.0f;
    }
    __syncthreads();

    // producer: thread -> (row = tid>>2, 16B-group = tid&3); B rows 0-63 and 64-127
    int prow = tid >> 2, pg = tid & 3;
    const __half* aptr = gh_x + (size_t)s_tok[prow] * HID + pg * 8;
    const __half* gp0 = gh_gate + (size_t)e * INTER * HID + (size_t)(ctile + prow) * HID + pg * 8;
    const __half* gp1 = gp0 + (size_t)64 * HID;
    const __half* up0 = gh_up + (size_t)e * INTER * HID + (size_t)(ctile + prow) * HID + pg * 8;
    const __half* up1 = up0 + (size_t)64 * HID;
    int sw_lo = swzi(prow, pg);
    int sw_hi = swzi(prow + 64, pg);

    // consumer constants
    int mg = (warp & 1) * 32, nh = (warp >> 1) * 32;
    int ly = lane >> 2, lx = lane & 3;
    int arl = (lane & 7) + ((lane >> 3) & 1) * 8;   // A ldm4 row-in-frag
    int akb = (lane >> 4) & 1;                      // A k-group select
    int brl = (lane & 7) + ((lane >> 4) & 1) * 8;   // B ldm4 row-in-frag
    int bkb = (lane >> 3) & 1;

    float accg[2][4][4] = {}, accu[2][4][4] = {};

    uint4 ra, rg0, rg1, ru0, ru1;
    ra  = *(const uint4*)aptr;
    rg0 = *(const uint4*)gp0;  rg1 = *(const uint4*)gp1;
    ru0 = *(const uint4*)up0;  ru1 = *(const uint4*)up1;
    sA[0][sw_lo] = ra;
    sG[0][sw_lo] = rg0;  sG[0][sw_hi] = rg1;
    sU[0][sw_lo] = ru0;  sU[0][sw_hi] = ru1;
    __syncthreads();

    const int NCH = HID / KC;   // 64
    for (int c = 0; c < NCH; c++) {
        int p = c & 1;
        if (c + 1 < NCH) {       // prefetch next chunk (latency hidden under MMAs)
            int ko = (c + 1) * KC;
            ra  = *(const uint4*)(aptr + ko);
            rg0 = *(const uint4*)(gp0 + ko);  rg1 = *(const uint4*)(gp1 + ko);
            ru0 = *(const uint4*)(up0 + ko);  ru1 = *(const uint4*)(up1 + ko);
        }
        #pragma unroll
        for (int ks = 0; ks < 2; ks++) {
            int kg = ks * 2;
            unsigned a[2][4], b[2][4];
            ldm4(a[0][0], a[0][1], a[0][2], a[0][3], &sA[p][swzi(mg + arl,      kg + akb)]);
            ldm4(a[1][0], a[1][1], a[1][2], a[1][3], &sA[p][swzi(mg + 16 + arl, kg + akb)]);
            // gate
            ldm4(b[0][0], b[0][1], b[0][2], b[0][3], &sG[p][swzi(nh + brl,      kg + bkb)]);
            ldm4(b[1][0], b[1][1], b[1][2], b[1][3], &sG[p][swzi(nh + 16 + brl, kg + bkb)]);
            #pragma unroll
            for (int mi = 0; mi < 2; mi++) {
                MMA_F16(accg[mi][0], a[mi], b[0][0], b[0][1]);
                MMA_F16(accg[mi][1], a[mi], b[0][2], b[0][3]);
                MMA_F16(accg[mi][2], a[mi], b[1][0], b[1][1]);
                MMA_F16(accg[mi][3], a[mi], b[1][2], b[1][3]);
            }
            // up (reuse b regs)
            ldm4(b[0][0], b[0][1], b[0][2], b[0][3], &sU[p][swzi(nh + brl,      kg + bkb)]);
            ldm4(b[1][0], b[1][1], b[1][2], b[1][3], &sU[p][swzi(nh + 16 + brl, kg + bkb)]);
            #pragma unroll
            for (int mi = 0; mi < 2; mi++) {
                MMA_F16(accu[mi][0], a[mi], b[0][0], b[0][1]);
                MMA_F16(accu[mi][1], a[mi], b[0][2], b[0][3]);
                MMA_F16(accu[mi][2], a[mi], b[1][0], b[1][1]);
                MMA_F16(accu[mi][3], a[mi], b[1][2], b[1][3]);
            }
        }
        __syncthreads();
        if (c + 1 < NCH) {
            int q = p ^ 1;
            sA[q][sw_lo] = ra;
            sG[q][sw_lo] = rg0;  sG[q][sw_hi] = rg1;
            sU[q][sw_lo] = ru0;  sU[q][sw_hi] = ru1;
        }
        __syncthreads();
    }

    // epilogue: silu(g)*u*w -> g_inter (fp16)
    #pragma unroll
    for (int mi = 0; mi < 2; mi++) {
        int r0 = mg + mi * 16 + ly, r1 = r0 + 8;
        #pragma unroll
        for (int nj = 0; nj < 4; nj++) {
            int cc = ctile + nh + nj * 8 + 2 * lx;
            if (r0 < cnt) {
                float w = s_w[r0];
                float ga = accg[mi][nj][0], ua = accu[mi][nj][0];
                float gb = accg[mi][nj][1], ub = accu[mi][nj][1];
                float o0 = ga / (1.0f + __expf(-ga)) * ua * w;
                float o1 = gb / (1.0f + __expf(-gb)) * ub * w;
                *(__half2*)&g_inter[(size_t)(ib + r0) * INTER + cc] = __floats2half2_rn(o0, o1);
            }
            if (r1 < cnt) {
                float w = s_w[r1];
                float ga = accg[mi][nj][2], ua = accu[mi][nj][2];
                float gb = accg[mi][nj][3], ub = accu[mi][nj][3];
                float o0 = ga / (1.0f + __expf(-ga)) * ua * w;
                float o1 = gb / (1.0f + __expf(-gb)) * ub * w;
                *(__half2*)&g_inter[(size_t)(ib + r1) * INTER + cc] = __floats2half2_rn(o0, o1);
            }
        }
    }
}

// ---------------- kernel 4: fp16 MMA down + scatter-add ----------------
// Block tile: 64 pairs x 128 hid cols. Warps 2(m) x 4(n), warp 32x32.
__global__ __launch_bounds__(256, 2) void k_down(float* __restrict__ out) {
    int tile = blockIdx.y;
    if (tile >= g_ntiles) return;
    int4 d = g_desc[tile];
    int e = d.x, rs = d.y, cnt = d.z, ib = d.w;
    int ctile = blockIdx.x * 128;

    __shared__ uint4 sA[2][256];   // 64 rows (inter pairs) x 32 halves
    __shared__ uint4 sB[2][512];   // 128 rows (hid cols) x 32 halves
    __shared__ int s_tok[TM];

    int tid = threadIdx.x, lane = tid & 31, warp = tid >> 5;
    if (tid < TM)
        s_tok[tid] = (tid < cnt) ? g_tok[e * NPAIR + rs + tid] : 0;
    __syncthreads();

    int prow = tid >> 2, pg = tid & 3;
    const __half* aptr = g_inter + (size_t)(ib + prow) * INTER + pg * 8;
    const __half* bp0 = gh_down + (size_t)e * HID * INTER + (size_t)(ctile + prow) * INTER + pg * 8;
    const __half* bp1 = bp0 + (size_t)64 * INTER;
    int sw_lo = swzi(prow, pg);
    int sw_hi = swzi(prow + 64, pg);

    int mg = (warp & 1) * 32, nh = (warp >> 1) * 32;
    int ly = lane >> 2, lx = lane & 3;
    int arl = (lane & 7) + ((lane >> 3) & 1) * 8;
    int akb = (lane >> 4) & 1;
    int brl = (lane & 7) + ((lane >> 4) & 1) * 8;
    int bkb = (lane >> 3) & 1;

    float acc[2][4][4] = {};

    uint4 ra, rb0, rb1;
    ra  = *(const uint4*)aptr;
    rb0 = *(const uint4*)bp0;  rb1 = *(const uint4*)bp1;
    sA[0][sw_lo] = ra;
    sB[0][sw_lo] = rb0;  sB[0][sw_hi] = rb1;
    __syncthreads();

    const int NCH = INTER / KC;   // 32
    for (int c = 0; c < NCH; c++) {
        int p = c & 1;
        if (c + 1 < NCH) {
            int ko = (c + 1) * KC;
            ra  = *(const uint4*)(aptr + ko);
            rb0 = *(const uint4*)(bp0 + ko);  rb1 = *(const uint4*)(bp1 + ko);
        }
        #pragma unroll
        for (int ks = 0; ks < 2; ks++) {
            int kg = ks * 2;
            unsigned a[2][4], b[2][4];
            ldm4(a[0][0], a[0][1], a[0][2], a[0][3], &sA[p][swzi(mg + arl,      kg + akb)]);
            ldm4(a[1][0], a[1][1], a[1][2], a[1][3], &sA[p][swzi(mg + 16 + arl, kg + akb)]);
            ldm4(b[0][0], b[0][1], b[0][2], b[0][3], &sB[p][swzi(nh + brl,      kg + bkb)]);
            ldm4(b[1][0], b[1][1], b[1][2], b[1][3], &sB[p][swzi(nh + 16 + brl, kg + bkb)]);
            #pragma unroll
            for (int mi = 0; mi < 2; mi++) {
                MMA_F16(acc[mi][0], a[mi], b[0][0], b[0][1]);
                MMA_F16(acc[mi][1], a[mi], b[0][2], b[0][3]);
                MMA_F16(acc[mi][2], a[mi], b[1][0], b[1][1]);
                MMA_F16(acc[mi][3], a[mi], b[1][2], b[1][3]);
            }
        }
        __syncthreads();
        if (c + 1 < NCH) {
            int q = p ^ 1;
            sA[q][sw_lo] = ra;
            sB[q][sw_lo] = rb0;  sB[q][sw_hi] = rb1;
        }
        __syncthreads();
    }

    #pragma unroll
    for (int mi = 0; mi < 2; mi++) {
        int r0 = mg + mi * 16 + ly, r1 = r0 + 8;
        #pragma unroll
        for (int nj = 0; nj < 4; nj++) {
            int cc = ctile + nh + nj * 8 + 2 * lx;
            if (r0 < cnt) {
                float* o = out + (size_t)s_tok[r0] * HID + cc;
                atomicAdd(o,     acc[mi][nj][0]);
                atomicAdd(o + 1, acc[mi][nj][1]);
            }
            if (r1 < cnt) {
                float* o = out + (size_t)s_tok[r1] * HID + cc;
                atomicAdd(o,     acc[mi][nj][2]);
                atomicAdd(o + 1, acc[mi][nj][3]);
            }
        }
    }
}

// ---------------- launch ----------------
extern "C" void kernel_launch(void* const* d_in, const int* in_sizes, int n_in,
                              void* d_out, int out_size) {
    const float* x    = (const float*)d_in[0];
    const int*   eidx = (const int*)d_in[1];
    const float* ewt  = (const float*)d_in[2];
    const float* gate = (const float*)d_in[3];
    const float* up   = (const float*)d_in[4];
    const float* down = (const float*)d_in[5];
    float* out = (float*)d_out;

    k_zero<<<2048, 256>>>(out);
    k_route<<<(NPAIR + 255) / 256, 256>>>(eidx, ewt);
    k_desc<<<1, 32>>>();
    k_cvtall<<<8192, 256>>>((const float4*)gate, (const float4*)up,
                            (const float4*)down, (const float4*)x);

    // max tiles = 4096/64 + 7 = 71 -> 72
    dim3 g2(INTER / 128, 72);
    k_gateup<<<g2, 256>>>();

    dim3 g3(HID / 128, 72);
    k_down<<<g3, 256>>>(out);
}

// round 7
// speedup vs baseline: 6.4667x; 1.2061x over previous
#include <cuda_runtime.h>
#include <cuda_fp16.h>
#include <math.h>
#include <cstdint>

// Problem constants
#define HID 2048
#define INTER 1024
#define NEXP 8
#define NTOK 2048
#define TOPK 2
#define NPAIR (NTOK * TOPK)   // 4096

#define TM 128                // pair-rows per tile
#define KC 32                 // K halves per chunk (64B per logical row)

// ---------------- device scratch ----------------
__device__ int    g_cnt[NEXP];
__device__ int    g_tok[NEXP * NPAIR];
__device__ float  g_wt[NEXP * NPAIR];
__device__ int4   g_desc[64];             // {expert, row_start, count, inter_base}
__device__ int    g_ntiles;
__device__ __half gh_x[NTOK * HID];
__device__ __half gh_gate[NEXP * INTER * HID];
__device__ __half gh_up[NEXP * INTER * HID];
__device__ __half gh_down[NEXP * HID * INTER];
__device__ __half g_inter[(NPAIR + TM) * INTER];

// ---------------- helpers ----------------
__device__ __forceinline__ void ldm4(unsigned& r0, unsigned& r1, unsigned& r2,
                                     unsigned& r3, const void* ptr) {
    unsigned addr = (unsigned)__cvta_generic_to_shared(ptr);
    asm volatile("ldmatrix.sync.aligned.m8n8.x4.shared.b16 {%0,%1,%2,%3}, [%4];"
                 : "=r"(r0), "=r"(r1), "=r"(r2), "=r"(r3) : "r"(addr));
}

#define MMA_F16(c, a, b0, b1)                                                 \
    asm volatile(                                                             \
        "mma.sync.aligned.m16n8k16.row.col.f32.f16.f16.f32 "                  \
        "{%0,%1,%2,%3}, {%4,%5,%6,%7}, {%8,%9}, {%0,%1,%2,%3};"               \
        : "+f"((c)[0]), "+f"((c)[1]), "+f"((c)[2]), "+f"((c)[3])              \
        : "r"((a)[0]), "r"((a)[1]), "r"((a)[2]), "r"((a)[3]), "r"(b0), "r"(b1))

#define CP16(dst, src)                                                        \
    asm volatile("cp.async.cg.shared.global [%0], [%1], 16;"                  \
                 :: "r"(dst), "l"(src))
#define CP_COMMIT() asm volatile("cp.async.commit_group;" ::: "memory")
#define CP_WAIT1()  asm volatile("cp.async.wait_group 1;" ::: "memory")

// Paired-row XOR swizzle: (row, 16B-group g in 0..3) -> uint4 index.
// Two 64B logical rows per 128B smem row; position XOR'd by (srow&7).
// Conflict-free for cp.async STS and all ldmatrix phases.
__device__ __forceinline__ int swzi(int row, int g) {
    int srow = row >> 1;
    return srow * 8 + ((((row & 1) << 2) | g) ^ (srow & 7));
}

// ---------------- kernel 0: zero output + counters ----------------
__global__ void k_zero(float* out) {
    int i = blockIdx.x * blockDim.x + threadIdx.x;
    int total = NTOK * HID;
    for (; i < total; i += gridDim.x * blockDim.x) out[i] = 0.0f;
    if (blockIdx.x == 0 && threadIdx.x < NEXP) g_cnt[threadIdx.x] = 0;
}

// ---------------- kernel 1: route ----------------
__global__ void k_route(const int* __restrict__ idx,
                        const float* __restrict__ wts) {
    int p = blockIdx.x * blockDim.x + threadIdx.x;
    if (p >= NPAIR) return;
    int e = idx[p] & 7;
    float w = wts[p];
    int pos = atomicAdd(&g_cnt[e], 1);
    g_tok[e * NPAIR + pos] = p >> 1;
    g_wt[e * NPAIR + pos] = w;
}

// ---------------- kernel 2: tile descriptors ----------------
__global__ void k_desc() {
    if (threadIdx.x != 0 || blockIdx.x != 0) return;
    int nt = 0, base = 0;
    for (int e = 0; e < NEXP; e++) {
        int c = g_cnt[e];
        for (int s = 0; s < c; s += TM) {
            int rows = c - s; if (rows > TM) rows = TM;
            g_desc[nt] = make_int4(e, s, rows, base + s);
            nt++;
        }
        base += c;
    }
    g_ntiles = nt;
}

// ---------------- kernel: fp32 -> fp16 pre-convert (weights + x) ----------
__global__ void k_cvtall(const float4* __restrict__ gate,
                         const float4* __restrict__ up,
                         const float4* __restrict__ down,
                         const float4* __restrict__ x) {
    const int NW8 = NEXP * INTER * HID / 8;
    const int NX8 = NTOK * HID / 8;
    int total = 3 * NW8 + NX8;
    for (int i = blockIdx.x * blockDim.x + threadIdx.x; i < total;
         i += gridDim.x * blockDim.x) {
        const float4* src; uint4* dst; int j;
        if (i < NW8)          { src = gate; dst = (uint4*)gh_gate; j = i; }
        else if (i < 2 * NW8) { src = up;   dst = (uint4*)gh_up;   j = i - NW8; }
        else if (i < 3 * NW8) { src = down; dst = (uint4*)gh_down; j = i - 2 * NW8; }
        else                  { src = x;    dst = (uint4*)gh_x;    j = i - 3 * NW8; }
        float4 f0 = src[2 * j], f1 = src[2 * j + 1];
        __half2 h0 = __floats2half2_rn(f0.x, f0.y);
        __half2 h1 = __floats2half2_rn(f0.z, f0.w);
        __half2 h2 = __floats2half2_rn(f1.x, f1.y);
        __half2 h3 = __floats2half2_rn(f1.z, f1.w);
        uint4 o;
        o.x = *(unsigned*)&h0; o.y = *(unsigned*)&h1;
        o.z = *(unsigned*)&h2; o.w = *(unsigned*)&h3;
        dst[j] = o;
    }
}

// ---------------- kernel 3: fp16 MMA gate+up + SwiGLU ----------------
// Block 128 pairs x 128 inter cols, 512 threads (4m x 4n warps, 32x32 each
// for BOTH gate and up). 3-stage cp.async pipeline.
// Dynamic smem layout (uint4 units): sA[3][512] | sG[3][512] | sU[3][512]
#define GU_A(s)  (0 + (s) * 512)
#define GU_G(s)  (1536 + (s) * 512)
#define GU_U(s)  (3072 + (s) * 512)
#define GU_TOKB  (4608 * 16)                  // byte offset of s_tok
#define GU_SMEM  (4608 * 16 + TM * 8 + 16)

__global__ __launch_bounds__(512, 1) void k_gateup() {
    int tile = blockIdx.y;
    if (tile >= g_ntiles) return;
    int4 d = g_desc[tile];
    int e = d.x, rs = d.y, cnt = d.z, ib = d.w;
    int ctile = blockIdx.x * 128;

    extern __shared__ uint4 smem[];
    int*   s_tok = (int*)((char*)smem + GU_TOKB);
    float* s_w   = (float*)(s_tok + TM);

    int tid = threadIdx.x, lane = tid & 31, warp = tid >> 5;
    if (tid < TM) {
        s_tok[tid] = (tid < cnt) ? g_tok[e * NPAIR + rs + tid] : g_tok[e * NPAIR + rs];
        s_w[tid]   = (tid < cnt) ? g_wt[e * NPAIR + rs + tid] : 0.0f;
    }
    __syncthreads();

    // producer: thread -> (row = tid>>2, 16B-group = tid&3), 1 cp.async per buf
    int prow = tid >> 2, pg = tid & 3;
    const __half* aptr = gh_x + (size_t)s_tok[prow] * HID + pg * 8;
    const __half* gptr = gh_gate + (size_t)e * INTER * HID + (size_t)(ctile + prow) * HID + pg * 8;
    const __half* uptr = gh_up   + (size_t)e * INTER * HID + (size_t)(ctile + prow) * HID + pg * 8;
    int swp = swzi(prow, pg);
    unsigned sbase = (unsigned)__cvta_generic_to_shared(smem);

    // consumer mapping
    int mg = (warp & 3) * 32, nh = (warp >> 2) * 32;
    int ly = lane >> 2, lx = lane & 3;
    int arl = (lane & 7) + ((lane >> 3) & 1) * 8;
    int akb = (lane >> 4) & 1;
    int brl = (lane & 7) + ((lane >> 4) & 1) * 8;
    int bkb = (lane >> 3) & 1;

    float accg[2][4][4] = {}, accu[2][4][4] = {};

    const int NCH = HID / KC;   // 64
    // prologue: stages 0,1 <- chunks 0,1
    #pragma unroll
    for (int s = 0; s < 2; s++) {
        int ko = s * KC;
        CP16(sbase + (GU_A(s) + swp) * 16, aptr + ko);
        CP16(sbase + (GU_G(s) + swp) * 16, gptr + ko);
        CP16(sbase + (GU_U(s) + swp) * 16, uptr + ko);
        CP_COMMIT();
    }

    for (int c = 0; c < NCH; c++) {
        int p = c % 3;
        CP_WAIT1();
        __syncthreads();

        const uint4* bA = smem + GU_A(p);
        const uint4* bG = smem + GU_G(p);
        const uint4* bU = smem + GU_U(p);
        #pragma unroll
        for (int ks = 0; ks < 2; ks++) {
            int kg = ks * 2;
            unsigned a[2][4], b[2][4];
            ldm4(a[0][0], a[0][1], a[0][2], a[0][3], bA + swzi(mg + arl,      kg + akb));
            ldm4(a[1][0], a[1][1], a[1][2], a[1][3], bA + swzi(mg + 16 + arl, kg + akb));
            ldm4(b[0][0], b[0][1], b[0][2], b[0][3], bG + swzi(nh + brl,      kg + bkb));
            ldm4(b[1][0], b[1][1], b[1][2], b[1][3], bG + swzi(nh + 16 + brl, kg + bkb));
            #pragma unroll
            for (int mi = 0; mi < 2; mi++) {
                MMA_F16(accg[mi][0], a[mi], b[0][0], b[0][1]);
                MMA_F16(accg[mi][1], a[mi], b[0][2], b[0][3]);
                MMA_F16(accg[mi][2], a[mi], b[1][0], b[1][1]);
                MMA_F16(accg[mi][3], a[mi], b[1][2], b[1][3]);
            }
            ldm4(b[0][0], b[0][1], b[0][2], b[0][3], bU + swzi(nh + brl,      kg + bkb));
            ldm4(b[1][0], b[1][1], b[1][2], b[1][3], bU + swzi(nh + 16 + brl, kg + bkb));
            #pragma unroll
            for (int mi = 0; mi < 2; mi++) {
                MMA_F16(accu[mi][0], a[mi], b[0][0], b[0][1]);
                MMA_F16(accu[mi][1], a[mi], b[0][2], b[0][3]);
                MMA_F16(accu[mi][2], a[mi], b[1][0], b[1][1]);
                MMA_F16(accu[mi][3], a[mi], b[1][2], b[1][3]);
            }
        }
        if (c + 2 < NCH) {
            int s = (c + 2) % 3;
            int ko = (c + 2) * KC;
            CP16(sbase + (GU_A(s) + swp) * 16, aptr + ko);
            CP16(sbase + (GU_G(s) + swp) * 16, gptr + ko);
            CP16(sbase + (GU_U(s) + swp) * 16, uptr + ko);
        }
        CP_COMMIT();
    }

    // epilogue: silu(g)*u*w -> g_inter (fp16)
    #pragma unroll
    for (int mi = 0; mi < 2; mi++) {
        int r0 = mg + mi * 16 + ly, r1 = r0 + 8;
        #pragma unroll
        for (int nj = 0; nj < 4; nj++) {
            int cc = ctile + nh + nj * 8 + 2 * lx;
            if (r0 < cnt) {
                float w = s_w[r0];
                float ga = accg[mi][nj][0], ua = accu[mi][nj][0];
                float gb = accg[mi][nj][1], ub = accu[mi][nj][1];
                float o0 = ga / (1.0f + __expf(-ga)) * ua * w;
                float o1 = gb / (1.0f + __expf(-gb)) * ub * w;
                *(__half2*)&g_inter[(size_t)(ib + r0) * INTER + cc] = __floats2half2_rn(o0, o1);
            }
            if (r1 < cnt) {
                float w = s_w[r1];
                float ga = accg[mi][nj][2], ua = accu[mi][nj][2];
                float gb = accg[mi][nj][3], ub = accu[mi][nj][3];
                float o0 = ga / (1.0f + __expf(-ga)) * ua * w;
                float o1 = gb / (1.0f + __expf(-gb)) * ub * w;
                *(__half2*)&g_inter[(size_t)(ib + r1) * INTER + cc] = __floats2half2_rn(o0, o1);
            }
        }
    }
}

// ---------------- kernel 4: fp16 MMA down + scatter-add ----------------
// Block 128 pairs x 128 hid cols, 512 threads. 3-stage cp.async pipeline.
#define DN_A(s)  (0 + (s) * 512)
#define DN_B(s)  (1536 + (s) * 512)
#define DN_TOKB  (3072 * 16)
#define DN_SMEM  (3072 * 16 + TM * 4 + 16)

__global__ __launch_bounds__(512, 1) void k_down(float* __restrict__ out) {
    int tile = blockIdx.y;
    if (tile >= g_ntiles) return;
    int4 d = g_desc[tile];
    int e = d.x, rs = d.y, cnt = d.z, ib = d.w;
    int ctile = blockIdx.x * 128;

    extern __shared__ uint4 smem[];
    int* s_tok = (int*)((char*)smem + DN_TOKB);

    int tid = threadIdx.x, lane = tid & 31, warp = tid >> 5;
    if (tid < TM)
        s_tok[tid] = (tid < cnt) ? g_tok[e * NPAIR + rs + tid] : 0;
    __syncthreads();

    int prow = tid >> 2, pg = tid & 3;
    const __half* aptr = g_inter + (size_t)(ib + prow) * INTER + pg * 8;
    const __half* bptr = gh_down + (size_t)e * HID * INTER + (size_t)(ctile + prow) * INTER + pg * 8;
    int swp = swzi(prow, pg);
    unsigned sbase = (unsigned)__cvta_generic_to_shared(smem);

    int mg = (warp & 3) * 32, nh = (warp >> 2) * 32;
    int ly = lane >> 2, lx = lane & 3;
    int arl = (lane & 7) + ((lane >> 3) & 1) * 8;
    int akb = (lane >> 4) & 1;
    int brl = (lane & 7) + ((lane >> 4) & 1) * 8;
    int bkb = (lane >> 3) & 1;

    float acc[2][4][4] = {};

    const int NCH = INTER / KC;   // 32
    #pragma unroll
    for (int s = 0; s < 2; s++) {
        int ko = s * KC;
        CP16(sbase + (DN_A(s) + swp) * 16, aptr + ko);
        CP16(sbase + (DN_B(s) + swp) * 16, bptr + ko);
        CP_COMMIT();
    }

    for (int c = 0; c < NCH; c++) {
        int p = c % 3;
        CP_WAIT1();
        __syncthreads();

        const uint4* bA = smem + DN_A(p);
        const uint4* bB = smem + DN_B(p);
        #pragma unroll
        for (int ks = 0; ks < 2; ks++) {
            int kg = ks * 2;
            unsigned a[2][4], b[2][4];
            ldm4(a[0][0], a[0][1], a[0][2], a[0][3], bA + swzi(mg + arl,      kg + akb));
            ldm4(a[1][0], a[1][1], a[1][2], a[1][3], bA + swzi(mg + 16 + arl, kg + akb));
            ldm4(b[0][0], b[0][1], b[0][2], b[0][3], bB + swzi(nh + brl,      kg + bkb));
            ldm4(b[1][0], b[1][1], b[1][2], b[1][3], bB + swzi(nh + 16 + brl, kg + bkb));
            #pragma unroll
            for (int mi = 0; mi < 2; mi++) {
                MMA_F16(acc[mi][0], a[mi], b[0][0], b[0][1]);
                MMA_F16(acc[mi][1], a[mi], b[0][2], b[0][3]);
                MMA_F16(acc[mi][2], a[mi], b[1][0], b[1][1]);
                MMA_F16(acc[mi][3], a[mi], b[1][2], b[1][3]);
            }
        }
        if (c + 2 < NCH) {
            int s = (c + 2) % 3;
            int ko = (c + 2) * KC;
            CP16(sbase + (DN_A(s) + swp) * 16, aptr + ko);
            CP16(sbase + (DN_B(s) + swp) * 16, bptr + ko);
        }
        CP_COMMIT();
    }

    #pragma unroll
    for (int mi = 0; mi < 2; mi++) {
        int r0 = mg + mi * 16 + ly, r1 = r0 + 8;
        #pragma unroll
        for (int nj = 0; nj < 4; nj++) {
            int cc = ctile + nh + nj * 8 + 2 * lx;
            if (r0 < cnt) {
                float* o = out + (size_t)s_tok[r0] * HID + cc;
                atomicAdd(o,     acc[mi][nj][0]);
                atomicAdd(o + 1, acc[mi][nj][1]);
            }
            if (r1 < cnt) {
                float* o = out + (size_t)s_tok[r1] * HID + cc;
                atomicAdd(o,     acc[mi][nj][2]);
                atomicAdd(o + 1, acc[mi][nj][3]);
            }
        }
    }
}

// ---------------- launch ----------------
extern "C" void kernel_launch(void* const* d_in, const int* in_sizes, int n_in,
                              void* d_out, int out_size) {
    const float* x    = (const float*)d_in[0];
    const int*   eidx = (const int*)d_in[1];
    const float* ewt  = (const float*)d_in[2];
    const float* gate = (const float*)d_in[3];
    const float* up   = (const float*)d_in[4];
    const float* down = (const float*)d_in[5];
    float* out = (float*)d_out;

    cudaFuncSetAttribute(k_gateup, cudaFuncAttributeMaxDynamicSharedMemorySize, GU_SMEM);
    cudaFuncSetAttribute(k_down,   cudaFuncAttributeMaxDynamicSharedMemorySize, DN_SMEM);

    k_zero<<<2048, 256>>>(out);
    k_route<<<(NPAIR + 255) / 256, 256>>>(eidx, ewt);
    k_desc<<<1, 32>>>();
    k_cvtall<<<8192, 256>>>((const float4*)gate, (const float4*)up,
                            (const float4*)down, (const float4*)x);

    // max tiles = 4096/128 + 7 = 39 -> 40
    dim3 g2(INTER / 128, 40);
    k_gateup<<<g2, 512, GU_SMEM>>>();

    dim3 g3(HID / 128, 40);
    k_down<<<g3, 512, DN_SMEM>>>(out);
}